// round 10
// baseline (speedup 1.0000x reference)
#include <cuda_runtime.h>
#include <cuda_bf16.h>
#include <cstdint>

#define BATCH 64
#define D 256
#define NTOK 4095
#define NCH 20             // 12 (layer1 K=768) + 4 (layer2) + 4 (layer3), K-chunk = 64

__device__ float g_node_val[2047 * BATCH * D];
__device__ __align__(256) uint4 g_W[NCH * 4096];   // 1.25 MB, fragment-major

// ---------------- SMEM layout ----------------
#define ASLOT   16896      // layer-1 A slot: hi 16*528 + lo 16*528 (aliases Af region)
#define ALO     8448
#define AFLO    32768      // Af lo offset
#define BIASOFF 65536
#define RPTROFF 68608
#define SMEM_TOTAL 70144

// ---------------- helpers ----------------
__device__ __forceinline__ void mma16816(float d[4], uint32_t a0, uint32_t a1, uint32_t a2, uint32_t a3,
                                         uint32_t b0, uint32_t b1) {
    asm volatile("mma.sync.aligned.m16n8k16.row.col.f32.bf16.bf16.f32 "
                 "{%0,%1,%2,%3}, {%4,%5,%6,%7}, {%8,%9}, {%0,%1,%2,%3};"
                 : "+f"(d[0]), "+f"(d[1]), "+f"(d[2]), "+f"(d[3])
                 : "r"(a0), "r"(a1), "r"(a2), "r"(a3), "r"(b0), "r"(b1));
}
__device__ __forceinline__ uint32_t b2u(__nv_bfloat162 v) { return *reinterpret_cast<uint32_t*>(&v); }
__device__ __forceinline__ uint32_t splith(float x, float y, uint32_t& l) {
    __nv_bfloat162 hh = __floats2bfloat162_rn(x, y);
    __nv_bfloat162 ll = __floats2bfloat162_rn(x - __bfloat162float(hh.x),
                                              y - __bfloat162float(hh.y));
    l = b2u(ll);
    return b2u(hh);
}

// -------- weight prep: fp32 -> hi/lo bf16, frag-major K64 chunks --------
// g_W[((gc*4+s)*32 + jt)*32 + lane] = {b0h, b1h, b0l, b1l}
__global__ void prep_weights(const float* __restrict__ W_in,
                             const float* __restrict__ W1,
                             const float* __restrict__ W2) {
    int idx = blockIdx.x * 256 + threadIdx.x;
    if (idx >= NCH * 4096) return;
    int lane = idx & 31;
    int jt   = (idx >> 5) & 31;
    int s    = (idx >> 10) & 3;
    int gcw  = idx >> 12;
    int n  = jt * 8 + (lane >> 2);
    int tg = lane & 3;
    const float* Wsrc; int K, kb;
    if (gcw < 12)      { Wsrc = W_in; K = 768; kb = gcw * 64; }
    else if (gcw < 16) { Wsrc = W1;   K = 256; kb = (gcw - 12) * 64; }
    else               { Wsrc = W2;   K = 256; kb = (gcw - 16) * 64; }
    int k0 = kb + s * 16 + tg * 2;
    uint32_t l0, l1;
    uint32_t h0 = splith(Wsrc[n * K + k0],     Wsrc[n * K + k0 + 1], l0);
    uint32_t h1 = splith(Wsrc[n * K + k0 + 8], Wsrc[n * K + k0 + 9], l1);
    g_W[idx] = make_uint4(h0, h1, l0, l1);
}

// Load one kstep-pair of B fragments (2 ksteps x 4 j-tiles = 8 uint4 = 32 regs).
// pairIdx in [0, 40): chunk = pairIdx>>1, kstep base = (pairIdx&1)*2.
__device__ __forceinline__ void loadBpair(uint4 B[8], int pairIdx, int wn, int lane) {
    const uint4* wp = g_W + ((size_t)pairIdx * 2048) + (wn * 4) * 32 + lane;
    B[0] = wp[0];    B[1] = wp[32];   B[2] = wp[64];   B[3] = wp[96];
    B[4] = wp[1024]; B[5] = wp[1056]; B[6] = wp[1088]; B[7] = wp[1120];
}

// ---------------- fused 3-layer MLP, M=64 node-block, 256 threads, 1 block/SM (deep ILP) ----------------
__global__ void __launch_bounds__(256, 1)
level_kernel(const int* __restrict__ tokens, const float* __restrict__ E,
             const float* __restrict__ b_in, const float* __restrict__ b1,
             const float* __restrict__ b2, float* __restrict__ d_out, int level)
{
    extern __shared__ char smem[];
    float* bias = (float*)(smem + BIASOFF);
    const float** rowptr = (const float**)(smem + RPTROFF);
    char* As = smem;     // layer-1 A ring (2 x ASLOT), aliases Af
    char* Af = smem;     // resident activations for layers 2-3

    const int tid  = threadIdx.x;
    const int wn   = tid >> 5;        // warp: 32 output cols
    const int lane = tid & 31;
    const int g    = lane >> 2;
    const int tig  = lane & 3;
    const int node = level - 1 + blockIdx.x;

    // gather decode: combo c = t*4+s (t = m16 tile, s = kstep), 16 threads per combo
    const int gc_  = tid >> 4;
    const int grg  = (tid >> 2) & 3;
    const int gtig = tid & 3;
    const int gr0  = (gc_ >> 2) * 16 + grg;
    const int gs   = gc_ & 3;

    bias[tid]       = b_in[tid];
    bias[256 + tid] = b1[tid];
    bias[512 + tid] = b2[tid];
    if (tid < 64) {
        int b = tid;
        rowptr[tid] = E + (size_t)tokens[b * NTOK + node] * D;
        if (level == 1024) {
            rowptr[64 + tid]  = E + (size_t)tokens[b * NTOK + 2 * node + 1] * D;
            rowptr[128 + tid] = E + (size_t)tokens[b * NTOK + 2 * node + 2] * D;
        } else {
            rowptr[64 + tid]  = g_node_val + ((size_t)(2 * node + 1) * BATCH + b) * D;
            rowptr[128 + tid] = g_node_val + ((size_t)(2 * node + 2) * BATCH + b) * D;
        }
    }

    float acc[4][4][4];
    #pragma unroll
    for (int i = 0; i < 4; ++i)
        #pragma unroll
        for (int j = 0; j < 4; ++j)
            #pragma unroll
            for (int q = 0; q < 4; ++q) acc[i][j][q] = 0.f;

    // B register pipeline: BufA / BufB alternate per kstep-pair
    uint4 BufA[8], BufB[8];
    loadBpair(BufA, 0, wn, lane);

    __syncthreads();   // rowptr visible

    // ---- A(0) gather: conflict-tuned STS.128 fragment lines ----
    {
        const float* pr0 = rowptr[gr0];
        const float* pr1 = rowptr[gr0 + 8];
        const float* pr2 = rowptr[gr0 + 4];
        const float* pr3 = rowptr[gr0 + 12];
        int kb = gs * 16 + gtig * 2;
        float2 a0 = *(const float2*)(pr0 + kb),     a1 = *(const float2*)(pr1 + kb);
        float2 a2 = *(const float2*)(pr0 + kb + 8), a3 = *(const float2*)(pr1 + kb + 8);
        float2 c0 = *(const float2*)(pr2 + kb),     c1 = *(const float2*)(pr3 + kb);
        float2 c2 = *(const float2*)(pr2 + kb + 8), c3 = *(const float2*)(pr3 + kb + 8);
        uint4 h1v, l1v, h2v, l2v;
        h1v.x = splith(a0.x, a0.y, l1v.x); h1v.y = splith(a1.x, a1.y, l1v.y);
        h1v.z = splith(a2.x, a2.y, l1v.z); h1v.w = splith(a3.x, a3.y, l1v.w);
        h2v.x = splith(c0.x, c0.y, l2v.x); h2v.y = splith(c1.x, c1.y, l2v.y);
        h2v.z = splith(c2.x, c2.y, l2v.z); h2v.w = splith(c3.x, c3.y, l2v.w);
        char* b1p = As + gc_ * 528 + (grg * 4 + gtig) * 16;
        char* b2p = As + gc_ * 528 + ((grg + 4) * 4 + gtig) * 16;
        *(uint4*)b1p = h1v; *(uint4*)(b1p + ALO) = l1v;
        *(uint4*)b2p = h2v; *(uint4*)(b2p + ALO) = l2v;
    }
    __syncthreads();

    // ================= unified chunk loop =================
    #pragma unroll 1
    for (int gcc = 0; gcc < NCH; ++gcc) {
        const int slot = gcc & 1;
        const bool doGather = (gcc + 1 < 12);
        const int layer = (gcc < 12) ? 0 : (gcc < 16) ? 1 : 2;
        const int cIn = (layer == 1) ? (gcc - 12) : (gcc - 16);

        // prefetch next-chunk A rows (registers; latency hidden under MMAs)
        float2 a0, a1, a2, a3, c0, c1, c2, c3;
        if (doGather) {
            int gn = gcc + 1;
            int seg = gn >> 2;
            int kb = (gn & 3) * 64 + gs * 16 + gtig * 2;
            const float* pr0 = rowptr[seg * 64 + gr0];
            const float* pr1 = rowptr[seg * 64 + gr0 + 8];
            const float* pr2 = rowptr[seg * 64 + gr0 + 4];
            const float* pr3 = rowptr[seg * 64 + gr0 + 12];
            a0 = *(const float2*)(pr0 + kb);     a1 = *(const float2*)(pr1 + kb);
            a2 = *(const float2*)(pr0 + kb + 8); a3 = *(const float2*)(pr1 + kb + 8);
            c0 = *(const float2*)(pr2 + kb);     c1 = *(const float2*)(pr3 + kb);
            c2 = *(const float2*)(pr2 + kb + 8); c3 = *(const float2*)(pr3 + kb + 8);
        }

        const char* ab = As + slot * ASLOT;

        // ---- kstep-pair 0 (ks 0,1): consume BufA, prefetch pair into BufB ----
        loadBpair(BufB, gcc * 2 + 1, wn, lane);
        #pragma unroll
        for (int ks = 0; ks < 2; ++ks) {
            uint4 Ahi[4], Alo[4];
            #pragma unroll
            for (int i = 0; i < 4; ++i) {
                const char* p = (layer == 0)
                    ? ab + (i * 4 + ks) * 528 + lane * 16
                    : Af + ((i * 16 + (cIn * 4 + ks)) * 32 + lane) * 16;
                Ahi[i] = *(const uint4*)p;
                Alo[i] = *(const uint4*)(p + (layer == 0 ? ALO : AFLO));
            }
            #pragma unroll
            for (int j = 0; j < 4; ++j) {
                uint4 B = BufA[ks * 4 + j];
                #pragma unroll
                for (int i = 0; i < 4; ++i) {
                    mma16816(acc[i][j], Ahi[i].x, Ahi[i].y, Ahi[i].z, Ahi[i].w, B.x, B.y);
                    mma16816(acc[i][j], Ahi[i].x, Ahi[i].y, Ahi[i].z, Ahi[i].w, B.z, B.w);
                    mma16816(acc[i][j], Alo[i].x, Alo[i].y, Alo[i].z, Alo[i].w, B.x, B.y);
                }
            }
        }
        // ---- kstep-pair 1 (ks 2,3): consume BufB, prefetch next chunk's pair 0 into BufA ----
        if (gcc + 1 < NCH) loadBpair(BufA, gcc * 2 + 2, wn, lane);
        #pragma unroll
        for (int ks = 2; ks < 4; ++ks) {
            uint4 Ahi[4], Alo[4];
            #pragma unroll
            for (int i = 0; i < 4; ++i) {
                const char* p = (layer == 0)
                    ? ab + (i * 4 + ks) * 528 + lane * 16
                    : Af + ((i * 16 + (cIn * 4 + ks)) * 32 + lane) * 16;
                Ahi[i] = *(const uint4*)p;
                Alo[i] = *(const uint4*)(p + (layer == 0 ? ALO : AFLO));
            }
            #pragma unroll
            for (int j = 0; j < 4; ++j) {
                uint4 B = BufB[(ks - 2) * 4 + j];
                #pragma unroll
                for (int i = 0; i < 4; ++i) {
                    mma16816(acc[i][j], Ahi[i].x, Ahi[i].y, Ahi[i].z, Ahi[i].w, B.x, B.y);
                    mma16816(acc[i][j], Ahi[i].x, Ahi[i].y, Ahi[i].z, Ahi[i].w, B.z, B.w);
                    mma16816(acc[i][j], Alo[i].x, Alo[i].y, Alo[i].z, Alo[i].w, B.x, B.y);
                }
            }
        }

        // store prefetched A into other slot (layer 1 only)
        if (doGather) {
            uint4 h1v, l1v, h2v, l2v;
            h1v.x = splith(a0.x, a0.y, l1v.x); h1v.y = splith(a1.x, a1.y, l1v.y);
            h1v.z = splith(a2.x, a2.y, l1v.z); h1v.w = splith(a3.x, a3.y, l1v.w);
            h2v.x = splith(c0.x, c0.y, l2v.x); h2v.y = splith(c1.x, c1.y, l2v.y);
            h2v.z = splith(c2.x, c2.y, l2v.z); h2v.w = splith(c3.x, c3.y, l2v.w);
            char* sb = As + (slot ^ 1) * ASLOT + gc_ * 528;
            char* b1p = sb + (grg * 4 + gtig) * 16;
            char* b2p = sb + ((grg + 4) * 4 + gtig) * 16;
            *(uint4*)b1p = h1v; *(uint4*)(b1p + ALO) = l1v;
            *(uint4*)b2p = h2v; *(uint4*)(b2p + ALO) = l2v;
        }
        if (layer == 0) __syncthreads();

        // ---- mid epilogues after layers 1 and 2: bias+ELU+split -> Af ----
        if (gcc == 11 || gcc == 15) {
            if (gcc == 15) __syncthreads();   // layer-2 reads of Af done before overwrite
            const float* bp = bias + ((gcc == 11) ? 0 : 256);
            #pragma unroll
            for (int i = 0; i < 4; ++i) {
                #pragma unroll
                for (int jp = 0; jp < 2; ++jp) {
                    uint4 hv, lv;
                    #pragma unroll
                    for (int u = 0; u < 2; ++u) {
                        int j = 2 * jp + u;
                        int cb = wn * 32 + j * 8 + tig * 2;
                        float b0v = bp[cb], b1v = bp[cb + 1];
                        float v0 = acc[i][j][0] + b0v, v1 = acc[i][j][1] + b1v;
                        float v2 = acc[i][j][2] + b0v, v3 = acc[i][j][3] + b1v;
                        v0 = v0 > 0.f ? v0 : (__expf(v0) - 1.f);
                        v1 = v1 > 0.f ? v1 : (__expf(v1) - 1.f);
                        v2 = v2 > 0.f ? v2 : (__expf(v2) - 1.f);
                        v3 = v3 > 0.f ? v3 : (__expf(v3) - 1.f);
                        if (u == 0) { hv.x = splith(v0, v1, lv.x); hv.y = splith(v2, v3, lv.y); }
                        else        { hv.z = splith(v0, v1, lv.z); hv.w = splith(v2, v3, lv.w); }
                        acc[i][j][0] = acc[i][j][1] = acc[i][j][2] = acc[i][j][3] = 0.f;
                    }
                    char* p = Af + ((i * 16 + wn * 2 + jp) * 32 + lane) * 16;
                    *(uint4*)p = hv;
                    *(uint4*)(p + AFLO) = lv;
                }
            }
            __syncthreads();
        }
    }

    // ---- final epilogue: acc + b2 + residual root embedding, direct stores ----
    #pragma unroll
    for (int i = 0; i < 4; ++i) {
        int r_g  = i * 16 + g;
        int r_g8 = r_g + 8;
        const float* e0p = rowptr[r_g];
        const float* e1p = rowptr[r_g8];
        #pragma unroll
        for (int j = 0; j < 4; ++j) {
            int cb = wn * 32 + j * 8 + tig * 2;
            float b0v = bias[512 + cb], b1v = bias[512 + cb + 1];
            float2 e0 = *(const float2*)(e0p + cb);
            float2 e1 = *(const float2*)(e1p + cb);
            float2 o0 = make_float2(acc[i][j][0] + b0v + e0.x, acc[i][j][1] + b1v + e0.y);
            float2 o1 = make_float2(acc[i][j][2] + b0v + e1.x, acc[i][j][3] + b1v + e1.y);
            if (level == 1) {
                *(float2*)(d_out + (size_t)r_g  * D + cb) = o0;
                *(float2*)(d_out + (size_t)r_g8 * D + cb) = o1;
            } else {
                *(float2*)(g_node_val + ((size_t)node * BATCH + r_g)  * D + cb) = o0;
                *(float2*)(g_node_val + ((size_t)node * BATCH + r_g8) * D + cb) = o1;
            }
        }
    }
}

extern "C" void kernel_launch(void* const* d_in, const int* in_sizes, int n_in,
                              void* d_out, int out_size) {
    const int*   tokens = (const int*)d_in[0];
    const float* E      = (const float*)d_in[1];
    const float* W_in   = (const float*)d_in[2];
    const float* b_in   = (const float*)d_in[3];
    const float* W1     = (const float*)d_in[4];
    const float* b1     = (const float*)d_in[5];
    const float* W2     = (const float*)d_in[6];
    const float* b2     = (const float*)d_in[7];
    float* out = (float*)d_out;

    cudaFuncSetAttribute(level_kernel, cudaFuncAttributeMaxDynamicSharedMemorySize, SMEM_TOTAL);

    prep_weights<<<(NCH * 4096) / 256, 256>>>(W_in, W1, W2);

    for (int level = 1024; level >= 1; level >>= 1) {
        level_kernel<<<level, 256, SMEM_TOTAL>>>(tokens, E, b_in, b1, b2, out, level);
    }
}

// round 11
// speedup vs baseline: 1.2983x; 1.2983x over previous
#include <cuda_runtime.h>
#include <cuda_bf16.h>
#include <cstdint>

#define BATCH 64
#define D 256
#define NTOK 4095
#define NCH 20             // 12 (layer1 K=768) + 4 (layer2) + 4 (layer3), K-chunk = 64

__device__ float g_node_val[2047 * BATCH * D];
__device__ __align__(256) uint4 g_W[NCH * 4096];   // 1.25 MB, fragment-major
// tail activation ping-pong: per node 4096 uint4 (hi 2048 | lo 2048), frag-major
__device__ __align__(256) uint4 g_actA[128 * 4096];
__device__ __align__(256) uint4 g_actB[128 * 4096];

// ---------------- SMEM layout (fused kernel) ----------------
#define ASLOT   16896      // layer-1 A slot: hi 16*528 + lo 16*528 (aliases Af region)
#define ALO     8448
#define AFLO    32768      // Af lo offset
#define BIASOFF 65536
#define RPTROFF 68608
#define SMEM_TOTAL 70144

// tail L1: As ring (2*ASLOT) + rowptr(192*8)
#define T1_RPTR   33792
#define T1_SMEM   35328
// tail L2/3: A stage 2 x 16KB + rowptr(64*8)
#define T2_RPTR   32768
#define T2_SMEM   33280

// ---------------- helpers ----------------
__device__ __forceinline__ uint32_t smem_u32(const void* p) {
    uint32_t a;
    asm("{ .reg .u64 t; cvta.to.shared.u64 t, %1; cvt.u32.u64 %0, t; }" : "=r"(a) : "l"(p));
    return a;
}
__device__ __forceinline__ void cp_async16(uint32_t dst, const void* src) {
    asm volatile("cp.async.cg.shared.global [%0], [%1], 16;" :: "r"(dst), "l"(src) : "memory");
}
__device__ __forceinline__ void cp_commit() { asm volatile("cp.async.commit_group;" ::: "memory"); }
template<int N> __device__ __forceinline__ void cp_wait() {
    asm volatile("cp.async.wait_group %0;" :: "n"(N) : "memory");
}
__device__ __forceinline__ void mma16816(float d[4], uint32_t a0, uint32_t a1, uint32_t a2, uint32_t a3,
                                         uint32_t b0, uint32_t b1) {
    asm volatile("mma.sync.aligned.m16n8k16.row.col.f32.bf16.bf16.f32 "
                 "{%0,%1,%2,%3}, {%4,%5,%6,%7}, {%8,%9}, {%0,%1,%2,%3};"
                 : "+f"(d[0]), "+f"(d[1]), "+f"(d[2]), "+f"(d[3])
                 : "r"(a0), "r"(a1), "r"(a2), "r"(a3), "r"(b0), "r"(b1));
}
__device__ __forceinline__ uint32_t b2u(__nv_bfloat162 v) { return *reinterpret_cast<uint32_t*>(&v); }
__device__ __forceinline__ uint32_t splith(float x, float y, uint32_t& l) {
    __nv_bfloat162 hh = __floats2bfloat162_rn(x, y);
    __nv_bfloat162 ll = __floats2bfloat162_rn(x - __bfloat162float(hh.x),
                                              y - __bfloat162float(hh.y));
    l = b2u(ll);
    return b2u(hh);
}
__device__ __forceinline__ float elu1(float v) { return v > 0.f ? v : (__expf(v) - 1.f); }

// -------- weight prep: fp32 -> hi/lo bf16, frag-major K64 chunks --------
__global__ void prep_weights(const float* __restrict__ W_in,
                             const float* __restrict__ W1,
                             const float* __restrict__ W2) {
    int idx = blockIdx.x * 256 + threadIdx.x;
    if (idx >= NCH * 4096) return;
    int lane = idx & 31;
    int jt   = (idx >> 5) & 31;
    int s    = (idx >> 10) & 3;
    int gcw  = idx >> 12;
    int n  = jt * 8 + (lane >> 2);
    int tg = lane & 3;
    const float* Wsrc; int K, kb;
    if (gcw < 12)      { Wsrc = W_in; K = 768; kb = gcw * 64; }
    else if (gcw < 16) { Wsrc = W1;   K = 256; kb = (gcw - 12) * 64; }
    else               { Wsrc = W2;   K = 256; kb = (gcw - 16) * 64; }
    int k0 = kb + s * 16 + tg * 2;
    uint32_t l0, l1;
    uint32_t h0 = splith(Wsrc[n * K + k0],     Wsrc[n * K + k0 + 1], l0);
    uint32_t h1 = splith(Wsrc[n * K + k0 + 8], Wsrc[n * K + k0 + 9], l1);
    g_W[idx] = make_uint4(h0, h1, l0, l1);
}

// B fragment LDG: 4 j-tiles for (chunk, kstep), warp-private slice, L2-resident
__device__ __forceinline__ void ldgB(uint4 B[4], int gc, int ks, int wn, int lane) {
    const uint4* wp = g_W + (((gc * 4 + ks) * 32) + wn * 4) * 32 + lane;
    B[0] = wp[0];
    B[1] = wp[32];
    B[2] = wp[64];
    B[3] = wp[96];
}

// ================= fused 3-layer kernel (levels >= 256), R8-proven =================
__global__ void __launch_bounds__(256, 2)
level_kernel(const int* __restrict__ tokens, const float* __restrict__ E,
             const float* __restrict__ b_in, const float* __restrict__ b1,
             const float* __restrict__ b2, float* __restrict__ d_out, int level)
{
    extern __shared__ char smem[];
    float* bias = (float*)(smem + BIASOFF);
    const float** rowptr = (const float**)(smem + RPTROFF);
    char* As = smem;
    char* Af = smem;

    const int tid  = threadIdx.x;
    const int wn   = tid >> 5;
    const int lane = tid & 31;
    const int g    = lane >> 2;
    const int tig  = lane & 3;
    const int node = level - 1 + blockIdx.x;

    const int gc_  = tid >> 4;
    const int grg  = (tid >> 2) & 3;
    const int gtig = tid & 3;
    const int gr0  = (gc_ >> 2) * 16 + grg;
    const int gs   = gc_ & 3;

    bias[tid]       = b_in[tid];
    bias[256 + tid] = b1[tid];
    bias[512 + tid] = b2[tid];
    if (tid < 64) {
        int b = tid;
        rowptr[tid] = E + (size_t)tokens[b * NTOK + node] * D;
        if (level == 1024) {
            rowptr[64 + tid]  = E + (size_t)tokens[b * NTOK + 2 * node + 1] * D;
            rowptr[128 + tid] = E + (size_t)tokens[b * NTOK + 2 * node + 2] * D;
        } else {
            rowptr[64 + tid]  = g_node_val + ((size_t)(2 * node + 1) * BATCH + b) * D;
            rowptr[128 + tid] = g_node_val + ((size_t)(2 * node + 2) * BATCH + b) * D;
        }
    }

    float acc[4][4][4];
    #pragma unroll
    for (int i = 0; i < 4; ++i)
        #pragma unroll
        for (int j = 0; j < 4; ++j)
            #pragma unroll
            for (int q = 0; q < 4; ++q) acc[i][j][q] = 0.f;

    __syncthreads();

    {
        const float* pr0 = rowptr[gr0];
        const float* pr1 = rowptr[gr0 + 8];
        const float* pr2 = rowptr[gr0 + 4];
        const float* pr3 = rowptr[gr0 + 12];
        int kb = gs * 16 + gtig * 2;
        float2 a0 = *(const float2*)(pr0 + kb),     a1 = *(const float2*)(pr1 + kb);
        float2 a2 = *(const float2*)(pr0 + kb + 8), a3 = *(const float2*)(pr1 + kb + 8);
        float2 c0 = *(const float2*)(pr2 + kb),     c1 = *(const float2*)(pr3 + kb);
        float2 c2 = *(const float2*)(pr2 + kb + 8), c3 = *(const float2*)(pr3 + kb + 8);
        uint4 h1v, l1v, h2v, l2v;
        h1v.x = splith(a0.x, a0.y, l1v.x); h1v.y = splith(a1.x, a1.y, l1v.y);
        h1v.z = splith(a2.x, a2.y, l1v.z); h1v.w = splith(a3.x, a3.y, l1v.w);
        h2v.x = splith(c0.x, c0.y, l2v.x); h2v.y = splith(c1.x, c1.y, l2v.y);
        h2v.z = splith(c2.x, c2.y, l2v.z); h2v.w = splith(c3.x, c3.y, l2v.w);
        char* b1p = As + gc_ * 528 + (grg * 4 + gtig) * 16;
        char* b2p = As + gc_ * 528 + ((grg + 4) * 4 + gtig) * 16;
        *(uint4*)b1p = h1v; *(uint4*)(b1p + ALO) = l1v;
        *(uint4*)b2p = h2v; *(uint4*)(b2p + ALO) = l2v;
    }
    __syncthreads();

    for (int gcc = 0; gcc < 12; ++gcc) {
        const int slot = gcc & 1;
        const bool doGather = (gcc + 1 < 12);

        float2 a0, a1, a2, a3, c0, c1, c2, c3;
        if (doGather) {
            int gn = gcc + 1;
            int seg = gn >> 2;
            int kb = (gn & 3) * 64 + gs * 16 + gtig * 2;
            const float* pr0 = rowptr[seg * 64 + gr0];
            const float* pr1 = rowptr[seg * 64 + gr0 + 8];
            const float* pr2 = rowptr[seg * 64 + gr0 + 4];
            const float* pr3 = rowptr[seg * 64 + gr0 + 12];
            a0 = *(const float2*)(pr0 + kb);     a1 = *(const float2*)(pr1 + kb);
            a2 = *(const float2*)(pr0 + kb + 8); a3 = *(const float2*)(pr1 + kb + 8);
            c0 = *(const float2*)(pr2 + kb);     c1 = *(const float2*)(pr3 + kb);
            c2 = *(const float2*)(pr2 + kb + 8); c3 = *(const float2*)(pr3 + kb + 8);
        }

        const char* ab = As + slot * ASLOT;
        uint4 B[4];
        ldgB(B, gcc, 0, wn, lane);
        #pragma unroll
        for (int ks = 0; ks < 4; ++ks) {
            uint4 Bn[4];
            if (ks < 3) ldgB(Bn, gcc, ks + 1, wn, lane);
            #pragma unroll
            for (int half = 0; half < 2; ++half) {
                uint4 Ahi[2], Alo[2];
                #pragma unroll
                for (int i2 = 0; i2 < 2; ++i2) {
                    const char* p = ab + ((half * 2 + i2) * 4 + ks) * 528 + lane * 16;
                    Ahi[i2] = *(const uint4*)p;
                    Alo[i2] = *(const uint4*)(p + ALO);
                }
                #pragma unroll
                for (int j = 0; j < 4; ++j)
                    #pragma unroll
                    for (int i2 = 0; i2 < 2; ++i2) {
                        float* a = acc[half * 2 + i2][j];
                        mma16816(a, Ahi[i2].x, Ahi[i2].y, Ahi[i2].z, Ahi[i2].w, B[j].x, B[j].y);
                        mma16816(a, Ahi[i2].x, Ahi[i2].y, Ahi[i2].z, Ahi[i2].w, B[j].z, B[j].w);
                        mma16816(a, Alo[i2].x, Alo[i2].y, Alo[i2].z, Alo[i2].w, B[j].x, B[j].y);
                    }
            }
            if (ks < 3) { B[0] = Bn[0]; B[1] = Bn[1]; B[2] = Bn[2]; B[3] = Bn[3]; }
        }

        if (doGather) {
            uint4 h1v, l1v, h2v, l2v;
            h1v.x = splith(a0.x, a0.y, l1v.x); h1v.y = splith(a1.x, a1.y, l1v.y);
            h1v.z = splith(a2.x, a2.y, l1v.z); h1v.w = splith(a3.x, a3.y, l1v.w);
            h2v.x = splith(c0.x, c0.y, l2v.x); h2v.y = splith(c1.x, c1.y, l2v.y);
            h2v.z = splith(c2.x, c2.y, l2v.z); h2v.w = splith(c3.x, c3.y, l2v.w);
            char* sb = As + (slot ^ 1) * ASLOT + gc_ * 528;
            char* b1p = sb + (grg * 4 + gtig) * 16;
            char* b2p = sb + ((grg + 4) * 4 + gtig) * 16;
            *(uint4*)b1p = h1v; *(uint4*)(b1p + ALO) = l1v;
            *(uint4*)b2p = h2v; *(uint4*)(b2p + ALO) = l2v;
        }
        __syncthreads();
    }

    // mid epilogue 1
    #pragma unroll
    for (int i = 0; i < 4; ++i) {
        #pragma unroll
        for (int jp = 0; jp < 2; ++jp) {
            uint4 hv, lv;
            #pragma unroll
            for (int u = 0; u < 2; ++u) {
                int j = 2 * jp + u;
                int cb = wn * 32 + j * 8 + tig * 2;
                float v0 = elu1(acc[i][j][0] + bias[cb]);
                float v1 = elu1(acc[i][j][1] + bias[cb + 1]);
                float v2 = elu1(acc[i][j][2] + bias[cb]);
                float v3 = elu1(acc[i][j][3] + bias[cb + 1]);
                if (u == 0) { hv.x = splith(v0, v1, lv.x); hv.y = splith(v2, v3, lv.y); }
                else        { hv.z = splith(v0, v1, lv.z); hv.w = splith(v2, v3, lv.w); }
                acc[i][j][0] = acc[i][j][1] = acc[i][j][2] = acc[i][j][3] = 0.f;
            }
            char* p = Af + ((i * 16 + wn * 2 + jp) * 32 + lane) * 16;
            *(uint4*)p = hv;
            *(uint4*)(p + AFLO) = lv;
        }
    }
    __syncthreads();

    // layers 2 & 3
    #pragma unroll 1
    for (int layer = 1; layer <= 2; ++layer) {
        const int gbase = (layer == 1) ? 12 : 16;
        #pragma unroll 1
        for (int c = 0; c < 4; ++c) {
            const int gcw = gbase + c;
            uint4 B[4];
            ldgB(B, gcw, 0, wn, lane);
            #pragma unroll
            for (int ks = 0; ks < 4; ++ks) {
                uint4 Bn[4];
                if (ks < 3) ldgB(Bn, gcw, ks + 1, wn, lane);
                int sg = c * 4 + ks;
                #pragma unroll
                for (int half = 0; half < 2; ++half) {
                    uint4 Ahi[2], Alo[2];
                    #pragma unroll
                    for (int i2 = 0; i2 < 2; ++i2) {
                        const char* p = Af + (((half * 2 + i2) * 16 + sg) * 32 + lane) * 16;
                        Ahi[i2] = *(const uint4*)p;
                        Alo[i2] = *(const uint4*)(p + AFLO);
                    }
                    #pragma unroll
                    for (int j = 0; j < 4; ++j)
                        #pragma unroll
                        for (int i2 = 0; i2 < 2; ++i2) {
                            float* a = acc[half * 2 + i2][j];
                            mma16816(a, Ahi[i2].x, Ahi[i2].y, Ahi[i2].z, Ahi[i2].w, B[j].x, B[j].y);
                            mma16816(a, Ahi[i2].x, Ahi[i2].y, Ahi[i2].z, Ahi[i2].w, B[j].z, B[j].w);
                            mma16816(a, Alo[i2].x, Alo[i2].y, Alo[i2].z, Alo[i2].w, B[j].x, B[j].y);
                        }
                }
                if (ks < 3) { B[0] = Bn[0]; B[1] = Bn[1]; B[2] = Bn[2]; B[3] = Bn[3]; }
            }
        }

        if (layer == 1) {
            __syncthreads();
            #pragma unroll
            for (int i = 0; i < 4; ++i) {
                #pragma unroll
                for (int jp = 0; jp < 2; ++jp) {
                    uint4 hv, lv;
                    #pragma unroll
                    for (int u = 0; u < 2; ++u) {
                        int j = 2 * jp + u;
                        int cb = wn * 32 + j * 8 + tig * 2;
                        float v0 = elu1(acc[i][j][0] + bias[256 + cb]);
                        float v1 = elu1(acc[i][j][1] + bias[256 + cb + 1]);
                        float v2 = elu1(acc[i][j][2] + bias[256 + cb]);
                        float v3 = elu1(acc[i][j][3] + bias[256 + cb + 1]);
                        if (u == 0) { hv.x = splith(v0, v1, lv.x); hv.y = splith(v2, v3, lv.y); }
                        else        { hv.z = splith(v0, v1, lv.z); hv.w = splith(v2, v3, lv.w); }
                        acc[i][j][0] = acc[i][j][1] = acc[i][j][2] = acc[i][j][3] = 0.f;
                    }
                    char* p = Af + ((i * 16 + wn * 2 + jp) * 32 + lane) * 16;
                    *(uint4*)p = hv;
                    *(uint4*)(p + AFLO) = lv;
                }
            }
            __syncthreads();
        }
    }

    // final epilogue
    #pragma unroll
    for (int i = 0; i < 4; ++i) {
        int r_g  = i * 16 + g;
        int r_g8 = r_g + 8;
        const float* e0p = rowptr[r_g];
        const float* e1p = rowptr[r_g8];
        #pragma unroll
        for (int j = 0; j < 4; ++j) {
            int cb = wn * 32 + j * 8 + tig * 2;
            float b0v = bias[512 + cb], b1v = bias[512 + cb + 1];
            float2 e0 = *(const float2*)(e0p + cb);
            float2 e1 = *(const float2*)(e1p + cb);
            float2 o0 = make_float2(acc[i][j][0] + b0v + e0.x, acc[i][j][1] + b1v + e0.y);
            float2 o1 = make_float2(acc[i][j][2] + b0v + e1.x, acc[i][j][3] + b1v + e1.y);
            *(float2*)(g_node_val + ((size_t)node * BATCH + r_g)  * D + cb) = o0;
            *(float2*)(g_node_val + ((size_t)node * BATCH + r_g8) * D + cb) = o1;
        }
    }
}

// ================= tail path (levels <= 128): per-layer, N split 4-ways =================

// ---- tail layer 1: K=768 from gathered inputs -> g_actA (frag-major hi/lo) ----
__global__ void __launch_bounds__(256, 2)
tail_l1(const int* __restrict__ tokens, const float* __restrict__ E,
        const float* __restrict__ b_in, int level)
{
    extern __shared__ char smem[];
    const float** rowptr = (const float**)(smem + T1_RPTR);
    char* As = smem;

    const int tid  = threadIdx.x;
    const int wn   = tid >> 5;        // warp: 8 output cols (1 j-tile)
    const int lane = tid & 31;
    const int g    = lane >> 2;
    const int tig  = lane & 3;
    const int nloc = blockIdx.x >> 2;
    const int cs4  = blockIdx.x & 3;  // 64-col slice
    const int node = level - 1 + nloc;
    const int jt   = cs4 * 8 + wn;    // global j-tile 0..31

    const int gc_  = tid >> 4;
    const int grg  = (tid >> 2) & 3;
    const int gtig = tid & 3;
    const int gr0  = (gc_ >> 2) * 16 + grg;
    const int gs   = gc_ & 3;

    if (tid < 64) {
        int b = tid;
        rowptr[tid]       = E + (size_t)tokens[b * NTOK + node] * D;
        rowptr[64 + tid]  = g_node_val + ((size_t)(2 * node + 1) * BATCH + b) * D;
        rowptr[128 + tid] = g_node_val + ((size_t)(2 * node + 2) * BATCH + b) * D;
    }

    float acc[4][4];
    #pragma unroll
    for (int i = 0; i < 4; ++i)
        #pragma unroll
        for (int q = 0; q < 4; ++q) acc[i][q] = 0.f;

    __syncthreads();
    {   // A(0) gather
        const float* pr0 = rowptr[gr0];
        const float* pr1 = rowptr[gr0 + 8];
        const float* pr2 = rowptr[gr0 + 4];
        const float* pr3 = rowptr[gr0 + 12];
        int kb = gs * 16 + gtig * 2;
        float2 a0 = *(const float2*)(pr0 + kb),     a1 = *(const float2*)(pr1 + kb);
        float2 a2 = *(const float2*)(pr0 + kb + 8), a3 = *(const float2*)(pr1 + kb + 8);
        float2 c0 = *(const float2*)(pr2 + kb),     c1 = *(const float2*)(pr3 + kb);
        float2 c2 = *(const float2*)(pr2 + kb + 8), c3 = *(const float2*)(pr3 + kb + 8);
        uint4 h1v, l1v, h2v, l2v;
        h1v.x = splith(a0.x, a0.y, l1v.x); h1v.y = splith(a1.x, a1.y, l1v.y);
        h1v.z = splith(a2.x, a2.y, l1v.z); h1v.w = splith(a3.x, a3.y, l1v.w);
        h2v.x = splith(c0.x, c0.y, l2v.x); h2v.y = splith(c1.x, c1.y, l2v.y);
        h2v.z = splith(c2.x, c2.y, l2v.z); h2v.w = splith(c3.x, c3.y, l2v.w);
        char* b1p = As + gc_ * 528 + (grg * 4 + gtig) * 16;
        char* b2p = As + gc_ * 528 + ((grg + 4) * 4 + gtig) * 16;
        *(uint4*)b1p = h1v; *(uint4*)(b1p + ALO) = l1v;
        *(uint4*)b2p = h2v; *(uint4*)(b2p + ALO) = l2v;
    }
    __syncthreads();

    for (int gcc = 0; gcc < 12; ++gcc) {
        const int slot = gcc & 1;
        const bool doGather = (gcc + 1 < 12);

        float2 a0, a1, a2, a3, c0, c1, c2, c3;
        if (doGather) {
            int gn = gcc + 1;
            int seg = gn >> 2;
            int kb = (gn & 3) * 64 + gs * 16 + gtig * 2;
            const float* pr0 = rowptr[seg * 64 + gr0];
            const float* pr1 = rowptr[seg * 64 + gr0 + 8];
            const float* pr2 = rowptr[seg * 64 + gr0 + 4];
            const float* pr3 = rowptr[seg * 64 + gr0 + 12];
            a0 = *(const float2*)(pr0 + kb);     a1 = *(const float2*)(pr1 + kb);
            a2 = *(const float2*)(pr0 + kb + 8); a3 = *(const float2*)(pr1 + kb + 8);
            c0 = *(const float2*)(pr2 + kb);     c1 = *(const float2*)(pr3 + kb);
            c2 = *(const float2*)(pr2 + kb + 8); c3 = *(const float2*)(pr3 + kb + 8);
        }

        const char* ab = As + slot * ASLOT;
        const uint4* wp = g_W + ((size_t)(gcc * 4) * 32 + jt) * 32 + lane;
        uint4 B = wp[0];
        #pragma unroll
        for (int ks = 0; ks < 4; ++ks) {
            uint4 Bn;
            if (ks < 3) Bn = wp[(ks + 1) * 1024];
            #pragma unroll
            for (int i = 0; i < 4; ++i) {
                const char* p = ab + (i * 4 + ks) * 528 + lane * 16;
                uint4 Ahi = *(const uint4*)p;
                uint4 Alo = *(const uint4*)(p + ALO);
                mma16816(acc[i], Ahi.x, Ahi.y, Ahi.z, Ahi.w, B.x, B.y);
                mma16816(acc[i], Ahi.x, Ahi.y, Ahi.z, Ahi.w, B.z, B.w);
                mma16816(acc[i], Alo.x, Alo.y, Alo.z, Alo.w, B.x, B.y);
            }
            if (ks < 3) B = Bn;
        }

        if (doGather) {
            uint4 h1v, l1v, h2v, l2v;
            h1v.x = splith(a0.x, a0.y, l1v.x); h1v.y = splith(a1.x, a1.y, l1v.y);
            h1v.z = splith(a2.x, a2.y, l1v.z); h1v.w = splith(a3.x, a3.y, l1v.w);
            h2v.x = splith(c0.x, c0.y, l2v.x); h2v.y = splith(c1.x, c1.y, l2v.y);
            h2v.z = splith(c2.x, c2.y, l2v.z); h2v.w = splith(c3.x, c3.y, l2v.w);
            char* sb = As + (slot ^ 1) * ASLOT + gc_ * 528;
            char* b1p = sb + (grg * 4 + gtig) * 16;
            char* b2p = sb + ((grg + 4) * 4 + gtig) * 16;
            *(uint4*)b1p = h1v; *(uint4*)(b1p + ALO) = l1v;
            *(uint4*)b2p = h2v; *(uint4*)(b2p + ALO) = l2v;
        }
        __syncthreads();
    }

    // epilogue: bias + ELU + split -> g_actA (uint2 half-lines)
    {
        int cb = cs4 * 64 + wn * 8 + tig * 2;
        float b0v = b_in[cb], b1v = b_in[cb + 1];
        int sg = cs4 * 4 + (wn >> 1);
        int hoff = (wn & 1) * 8;
        #pragma unroll
        for (int i = 0; i < 4; ++i) {
            float v0 = elu1(acc[i][0] + b0v);
            float v1 = elu1(acc[i][1] + b1v);
            float v2 = elu1(acc[i][2] + b0v);
            float v3 = elu1(acc[i][3] + b1v);
            uint32_t lx, ly;
            uint32_t hx = splith(v0, v1, lx);
            uint32_t hy = splith(v2, v3, ly);
            char* dst = (char*)(g_actA + (size_t)nloc * 4096 + (i * 16 + sg) * 32 + lane) + hoff;
            *(uint2*)dst = make_uint2(hx, hy);
            *(uint2*)(dst + 2048 * 16) = make_uint2(lx, ly);
        }
    }
}

// ---- tail layers 2/3: A from g_act via cp.async, K=256 ----
__global__ void __launch_bounds__(256, 2)
tail_l23(const int* __restrict__ tokens, const float* __restrict__ E,
         const float* __restrict__ bp, float* __restrict__ d_out, int level, int phase)
{
    extern __shared__ char smem[];
    const float** rowptr = (const float**)(smem + T2_RPTR);
    const uint32_t sb = smem_u32(smem);

    const int tid  = threadIdx.x;
    const int wn   = tid >> 5;
    const int lane = tid & 31;
    const int g    = lane >> 2;
    const int tig  = tid & 3;
    const int nloc = blockIdx.x >> 2;
    const int cs4  = blockIdx.x & 3;
    const int node = level - 1 + nloc;
    const int jt   = cs4 * 8 + wn;
    const int gbase = phase ? 16 : 12;
    const uint4* actSrc = (phase ? g_actB : g_actA) + (size_t)nloc * 4096;

    if (phase && tid < 64)
        rowptr[tid] = E + (size_t)tokens[tid * NTOK + node] * D;

    float acc[4][4];
    #pragma unroll
    for (int i = 0; i < 4; ++i)
        #pragma unroll
        for (int q = 0; q < 4; ++q) acc[i][q] = 0.f;

    // chunk copy helper (inline): chunk c -> slot (c&1)
    const int cidx = tid;   // 0..255
    // preload chunk 0
    #pragma unroll
    for (int r = 0; r < 4; ++r) {
        int idx = r * 256 + cidx;
        int part = idx >> 9, w = idx & 511, i = w >> 7, off = w & 127;
        cp_async16(sb + idx * 16, (const void*)(actSrc + part * 2048 + i * 512 + off));
    }
    cp_commit();

    #pragma unroll 1
    for (int c = 0; c < 4; ++c) {
        if (c + 1 < 4) {
            uint32_t dstb = sb + ((c + 1) & 1) * 16384;
            #pragma unroll
            for (int r = 0; r < 4; ++r) {
                int idx = r * 256 + cidx;
                int part = idx >> 9, w = idx & 511, i = w >> 7, off = w & 127;
                cp_async16(dstb + idx * 16,
                           (const void*)(actSrc + part * 2048 + i * 512 + (c + 1) * 128 + off));
            }
            cp_commit();
            cp_wait<1>();
        } else {
            cp_wait<0>();
        }
        __syncthreads();

        const uint4* slot = (const uint4*)(smem + (c & 1) * 16384);
        const uint4* wp = g_W + ((size_t)((gbase + c) * 4) * 32 + jt) * 32 + lane;
        uint4 B = wp[0];
        #pragma unroll
        for (int ks = 0; ks < 4; ++ks) {
            uint4 Bn;
            if (ks < 3) Bn = wp[(ks + 1) * 1024];
            #pragma unroll
            for (int i = 0; i < 4; ++i) {
                uint4 Ahi = slot[i * 128 + ks * 32 + lane];
                uint4 Alo = slot[512 + i * 128 + ks * 32 + lane];
                mma16816(acc[i], Ahi.x, Ahi.y, Ahi.z, Ahi.w, B.x, B.y);
                mma16816(acc[i], Ahi.x, Ahi.y, Ahi.z, Ahi.w, B.z, B.w);
                mma16816(acc[i], Alo.x, Alo.y, Alo.z, Alo.w, B.x, B.y);
            }
            if (ks < 3) B = Bn;
        }
        __syncthreads();
    }

    int cb = cs4 * 64 + wn * 8 + tig * 2;
    float b0v = bp[cb], b1v = bp[cb + 1];
    if (phase == 0) {
        int sg = cs4 * 4 + (wn >> 1);
        int hoff = (wn & 1) * 8;
        #pragma unroll
        for (int i = 0; i < 4; ++i) {
            float v0 = elu1(acc[i][0] + b0v);
            float v1 = elu1(acc[i][1] + b1v);
            float v2 = elu1(acc[i][2] + b0v);
            float v3 = elu1(acc[i][3] + b1v);
            uint32_t lx, ly;
            uint32_t hx = splith(v0, v1, lx);
            uint32_t hy = splith(v2, v3, ly);
            char* dst = (char*)(g_actB + (size_t)nloc * 4096 + (i * 16 + sg) * 32 + lane) + hoff;
            *(uint2*)dst = make_uint2(hx, hy);
            *(uint2*)(dst + 2048 * 16) = make_uint2(lx, ly);
        }
    } else {
        #pragma unroll
        for (int i = 0; i < 4; ++i) {
            int r0 = i * 16 + g, r1 = r0 + 8;
            float2 e0 = *(const float2*)(rowptr[r0] + cb);
            float2 e1 = *(const float2*)(rowptr[r1] + cb);
            float2 o0 = make_float2(acc[i][0] + b0v + e0.x, acc[i][1] + b1v + e0.y);
            float2 o1 = make_float2(acc[i][2] + b0v + e1.x, acc[i][3] + b1v + e1.y);
            if (level == 1) {
                *(float2*)(d_out + (size_t)r0 * D + cb) = o0;
                *(float2*)(d_out + (size_t)r1 * D + cb) = o1;
            } else {
                *(float2*)(g_node_val + ((size_t)node * BATCH + r0) * D + cb) = o0;
                *(float2*)(g_node_val + ((size_t)node * BATCH + r1) * D + cb) = o1;
            }
        }
    }
}

extern "C" void kernel_launch(void* const* d_in, const int* in_sizes, int n_in,
                              void* d_out, int out_size) {
    const int*   tokens = (const int*)d_in[0];
    const float* E      = (const float*)d_in[1];
    const float* W_in   = (const float*)d_in[2];
    const float* b_in   = (const float*)d_in[3];
    const float* W1     = (const float*)d_in[4];
    const float* b1     = (const float*)d_in[5];
    const float* W2     = (const float*)d_in[6];
    const float* b2     = (const float*)d_in[7];
    float* out = (float*)d_out;

    cudaFuncSetAttribute(level_kernel, cudaFuncAttributeMaxDynamicSharedMemorySize, SMEM_TOTAL);
    cudaFuncSetAttribute(tail_l1,  cudaFuncAttributeMaxDynamicSharedMemorySize, T1_SMEM);
    cudaFuncSetAttribute(tail_l23, cudaFuncAttributeMaxDynamicSharedMemorySize, T2_SMEM);

    prep_weights<<<(NCH * 4096) / 256, 256>>>(W_in, W1, W2);

    for (int level = 1024; level >= 256; level >>= 1)
        level_kernel<<<level, 256, SMEM_TOTAL>>>(tokens, E, b_in, b1, b2, out, level);

    for (int level = 128; level >= 1; level >>= 1) {
        tail_l1 <<<level * 4, 256, T1_SMEM>>>(tokens, E, b_in, level);
        tail_l23<<<level * 4, 256, T2_SMEM>>>(tokens, E, b1, out, level, 0);
        tail_l23<<<level * 4, 256, T2_SMEM>>>(tokens, E, b2, out, level, 1);
    }
}